// round 10
// baseline (speedup 1.0000x reference)
#include <cuda_runtime.h>
#include <cstdint>

// GraphConvolutionSparse: out = adj @ (inputs @ W)
//   inputs [16384,512] f32, adj [16384,16384] f32, weights [512,128] f32 -> out [16384,128] f32
// Warp-specialized TF32 mma.sync GEMM.
//   producers (4 warps): LDG.128 -> cvt.rna.tf32 -> STS.128 (conflict-free chunk mapping)
//   consumers (8 warps): ldmatrix/LDS -> mma (fragments pre-rounded; double-buffered)

#define N_ROWS 16384
#define D_IN   512
#define D_OUT  128

__device__ float g_X[N_ROWS * D_OUT];   // X = inputs @ W

namespace {

constexpr int BM = 128, BN = 128, BK = 32;
constexpr int AS = BK + 4;     // 36 floats/row (A tile)
constexpr int BS = BN + 8;     // 136 floats/row (B tile)
constexpr int A_SZ = BM * AS;  // 4608 floats
constexpr int B_SZ = BK * BS;  // 4352 floats
constexpr int BUF  = A_SZ + B_SZ;          // 8960 floats / stage
constexpr int NSTAGE = 5;
constexpr int CTRL_F = 256;                // 1024 B control region (mbarriers)
constexpr int SMEM_BYTES = (CTRL_F + NSTAGE * BUF) * 4;   // 180224 B

constexpr int NCONS = 8;                   // consumer warps
constexpr int NPROD = 4;                   // producer warps
constexpr int NTHREADS = (NCONS + NPROD) * 32;  // 384

__device__ __forceinline__ uint32_t f2tf32(float f) {
    uint32_t r;
    asm("cvt.rna.tf32.f32 %0, %1;" : "=r"(r) : "f"(f));
    return r;
}

__device__ __forceinline__ void mbar_init(uint32_t addr, uint32_t cnt) {
    asm volatile("mbarrier.init.shared.b64 [%0], %1;" :: "r"(addr), "r"(cnt) : "memory");
}

__device__ __forceinline__ void mbar_arrive(uint32_t addr) {
    asm volatile("mbarrier.arrive.release.cta.shared::cta.b64 _, [%0];"
                 :: "r"(addr) : "memory");
}

__device__ __forceinline__ void mbar_wait(uint32_t mbar, uint32_t parity) {
    asm volatile(
        "{\n\t.reg .pred P1;\n\t"
        "LWAIT_%=:\n\t"
        "mbarrier.try_wait.parity.acquire.cta.shared::cta.b64 P1, [%0], %1, 0x989680;\n\t"
        "@P1 bra LDONE_%=;\n\t"
        "bra LWAIT_%=;\n\t"
        "LDONE_%=:\n\t}"
        :: "r"(mbar), "r"(parity) : "memory");
}

// ldmatrix x4 on f32 data: each m8n8.b16 tile == 8 rows x 4 f32 (16B rows);
// thread t gets element (t/4, t%4) of each tile.
__device__ __forceinline__ void ldsm_x4(uint32_t& r0, uint32_t& r1,
                                        uint32_t& r2, uint32_t& r3, uint32_t addr) {
    asm volatile("ldmatrix.sync.aligned.m8n8.x4.shared.b16 {%0,%1,%2,%3}, [%4];"
                 : "=r"(r0), "=r"(r1), "=r"(r2), "=r"(r3) : "r"(addr));
}

__device__ __forceinline__ void mma_tf32(float& c0, float& c1, float& c2, float& c3,
                                         uint32_t a0, uint32_t a1, uint32_t a2, uint32_t a3,
                                         uint32_t b0, uint32_t b1) {
    asm volatile(
        "mma.sync.aligned.m16n8k8.row.col.f32.tf32.tf32.f32 "
        "{%0,%1,%2,%3}, {%4,%5,%6,%7}, {%8,%9}, {%0,%1,%2,%3};"
        : "+f"(c0), "+f"(c1), "+f"(c2), "+f"(c3)
        : "r"(a0), "r"(a1), "r"(a2), "r"(a3), "r"(b0), "r"(b1));
}

} // namespace

// C[M,BN] = A[M,K] @ B[K,BN]; A row-major (lda), B row-major (BN). grid.x=M/BM.
__global__ __launch_bounds__(NTHREADS, 1)
void gemm_ws_tf32(float* __restrict__ C, const float* __restrict__ A,
                  const float* __restrict__ B, int K, size_t lda) {
    extern __shared__ __align__(1024) float smem[];
    const int tid = threadIdx.x, wid = tid >> 5, lane = tid & 31;
    const int m0 = blockIdx.x * BM;
    const uint32_t sbase = (uint32_t)__cvta_generic_to_shared(smem);
    const uint32_t dbase = sbase + CTRL_F * 4;
    const int KT = K / BK;

    // mbarriers: full[s] @ sbase+16s (count=NPROD), empty[s] @ +8 (count=NCONS)
    if (tid == 0) {
        #pragma unroll
        for (int s = 0; s < NSTAGE; ++s) {
            mbar_init(sbase + 16 * s,     NPROD);
            mbar_init(sbase + 16 * s + 8, NCONS);
        }
    }
    __syncthreads();

    if (wid >= NCONS) {
        // ------- producers (4 warps): LDG -> cvt.rna -> STS, chunk mapping -------
        const int pt = tid - NCONS * 32;          // 0..127
        const float* Ab = A + (size_t)m0 * lda;

        // A chunks: c = i*128+pt -> row=c>>3 (0..127), ch=c&7
        // B chunks: c = i*128+pt -> row=c>>5 (0..31),  ch=c&31
        int arow[8], ach[8], brow[8], bch[8];
        #pragma unroll
        for (int i = 0; i < 8; ++i) {
            const int c = i * 128 + pt;
            arow[i] = c >> 3; ach[i] = c & 7;
            brow[i] = c >> 5; bch[i] = c & 31;
        }

        float4 abuf[8], bbuf[8];

        auto ldg = [&](int kt) {
            const float* Ak = Ab + (size_t)kt * BK;
            const float* Bk = B + (size_t)(kt * BK) * BN;
            #pragma unroll
            for (int i = 0; i < 8; ++i)
                abuf[i] = *(const float4*)(Ak + (size_t)arow[i] * lda + ach[i] * 4);
            #pragma unroll
            for (int i = 0; i < 8; ++i)
                bbuf[i] = *(const float4*)(Bk + (size_t)brow[i] * BN + bch[i] * 4);
        };

        auto sts = [&](int s) {
            float* dA = smem + CTRL_F + s * BUF;
            float* dB = dA + A_SZ;
            #pragma unroll
            for (int i = 0; i < 8; ++i) {
                uint4 t;
                t.x = f2tf32(abuf[i].x); t.y = f2tf32(abuf[i].y);
                t.z = f2tf32(abuf[i].z); t.w = f2tf32(abuf[i].w);
                *(uint4*)(dA + arow[i] * AS + ach[i] * 4) = t;
            }
            #pragma unroll
            for (int i = 0; i < 8; ++i) {
                uint4 t;
                t.x = f2tf32(bbuf[i].x); t.y = f2tf32(bbuf[i].y);
                t.z = f2tf32(bbuf[i].z); t.w = f2tf32(bbuf[i].w);
                *(uint4*)(dB + brow[i] * BS + bch[i] * 4) = t;
            }
        };

        ldg(0);
        for (int kt = 0; kt < KT; ++kt) {
            const int s = kt % NSTAGE;
            if (kt >= NSTAGE)
                mbar_wait(sbase + 16 * s + 8, (uint32_t)((kt / NSTAGE - 1) & 1));
            sts(s);
            __syncwarp();
            if (lane == 0) mbar_arrive(sbase + 16 * s);
            if (kt + 1 < KT) ldg(kt + 1);
        }
    } else {
        // ------- consumers (8 warps): ldsm/LDS -> mma, double-buffered frags -------
        const int wr = wid >> 2;              // 0..1 (64 rows each)
        const int wc = wid & 3;               // 0..3 (32 cols each)
        const int gid = lane >> 2, tig = lane & 3;
        const int lm_row = wr * 64 + (lane & 7) + ((lane >> 3) & 1) * 8;
        const int lm_k   = ((lane >> 3) >> 1) * 4;

        float acc[4][4][4];
        #pragma unroll
        for (int mi = 0; mi < 4; ++mi)
            #pragma unroll
            for (int ni = 0; ni < 4; ++ni)
                #pragma unroll
                for (int r = 0; r < 4; ++r) acc[mi][ni][r] = 0.0f;

        uint32_t a[2][4][4], b[2][4][2];

        for (int kt = 0; kt < KT; ++kt) {
            const int s = kt % NSTAGE;
            mbar_wait(sbase + 16 * s, (uint32_t)((kt / NSTAGE) & 1));

            const uint32_t aBase = dbase + (uint32_t)(s * BUF + lm_row * AS + lm_k) * 4u;
            const uint32_t* Bu = (const uint32_t*)(smem + CTRL_F + s * BUF + A_SZ);

            auto load_frag = [&](int kk, int d) {
                #pragma unroll
                for (int mi = 0; mi < 4; ++mi)
                    ldsm_x4(a[d][mi][0], a[d][mi][1], a[d][mi][2], a[d][mi][3],
                            aBase + (uint32_t)(mi * 16 * AS + kk) * 4u);
                #pragma unroll
                for (int ni = 0; ni < 4; ++ni) {
                    const int c = wc * 32 + ni * 8 + gid;
                    b[d][ni][0] = Bu[(kk + tig) * BS + c];
                    b[d][ni][1] = Bu[(kk + tig + 4) * BS + c];
                }
            };

            load_frag(0, 0);
            #pragma unroll
            for (int kq = 0; kq < 4; ++kq) {
                const int d = kq & 1;
                if (kq < 3) load_frag((kq + 1) * 8, d ^ 1);
                #pragma unroll
                for (int mi = 0; mi < 4; ++mi)
                    #pragma unroll
                    for (int ni = 0; ni < 4; ++ni)
                        mma_tf32(acc[mi][ni][0], acc[mi][ni][1], acc[mi][ni][2], acc[mi][ni][3],
                                 a[d][mi][0], a[d][mi][1], a[d][mi][2], a[d][mi][3],
                                 b[d][ni][0], b[d][ni][1]);
            }
            __syncwarp();
            if (lane == 0) mbar_arrive(sbase + 16 * s + 8);
        }

        // epilogue
        #pragma unroll
        for (int mi = 0; mi < 4; ++mi) {
            #pragma unroll
            for (int ni = 0; ni < 4; ++ni) {
                const int row = m0 + wr * 64 + mi * 16 + gid;
                const int col = wc * 32 + ni * 8 + tig * 2;
                *(float2*)(C + (size_t)row * BN + col) =
                    make_float2(acc[mi][ni][0], acc[mi][ni][1]);
                *(float2*)(C + (size_t)(row + 8) * BN + col) =
                    make_float2(acc[mi][ni][2], acc[mi][ni][3]);
            }
        }
    }
}

extern "C" void kernel_launch(void* const* d_in, const int* in_sizes, int n_in,
                              void* d_out, int out_size) {
    const float* inputs  = (const float*)d_in[0];   // [16384, 512]
    const float* adj     = (const float*)d_in[1];   // [16384, 16384]
    const float* weights = (const float*)d_in[2];   // [512, 128]
    float* out = (float*)d_out;                     // [16384, 128]
    (void)in_sizes; (void)n_in; (void)out_size;

    cudaFuncSetAttribute(gemm_ws_tf32,
                         cudaFuncAttributeMaxDynamicSharedMemorySize, SMEM_BYTES);

    float* X = nullptr;
    cudaGetSymbolAddress((void**)&X, g_X);

    // G1: X = inputs @ W    (K=512)
    gemm_ws_tf32<<<N_ROWS / BM, NTHREADS, SMEM_BYTES>>>(X, inputs, weights, D_IN, D_IN);
    // G2: out = adj @ X     (K=16384)
    gemm_ws_tf32<<<N_ROWS / BM, NTHREADS, SMEM_BYTES>>>(out, adj, X, N_ROWS, N_ROWS);
}

// round 11
// speedup vs baseline: 1.2083x; 1.2083x over previous
#include <cuda_runtime.h>
#include <cstdint>

// GraphConvolutionSparse: out = adj @ (inputs @ W)
//   inputs [16384,512] f32, adj [16384,16384] f32, weights [512,128] f32 -> out [16384,128] f32
// Warp-specialized TF32 mma.sync GEMM, BK=64.
//   producers (4 warps): cp.async raw f32 tiles
//   consumers (8 warps): ldmatrix/LDS -> (cvt.rna A; B pre-rounded) -> mma, double-buffered frags
// G1 writes X pre-rounded to tf32 bits so G2 needs no B-side cvt.

#define N_ROWS 16384
#define D_IN   512
#define D_OUT  128

__device__ float g_X[N_ROWS * D_OUT];   // X = inputs @ W (tf32-rounded bits)

namespace {

constexpr int BM = 128, BN = 128, BK = 64;
constexpr int AS = BK + 4;     // 68 floats/row (A tile): 68%32=4 -> ldsm conflict-free
constexpr int BS = BN + 8;     // 136 floats/row (B tile): 136%32=8 -> LDS conflict-free
constexpr int A_SZ = BM * AS;  // 8704 floats
constexpr int B_SZ = BK * BS;  // 8704 floats
constexpr int BUF  = A_SZ + B_SZ;          // 17408 floats / stage
constexpr int NSTAGE = 3;
constexpr int CTRL_F = 256;                // 1024 B control region (mbarriers)
constexpr int SMEM_BYTES = (CTRL_F + NSTAGE * BUF) * 4;   // 209920 B

constexpr int NCONS = 8;                   // consumer warps
constexpr int NPROD_THREADS = 128;         // 4 producer warps
constexpr int NTHREADS = NCONS * 32 + NPROD_THREADS;  // 384

// flags bit0: cvt B fragments in consumer (B not pre-rounded)
// flags bit1: round C to tf32 bits in epilogue (producing pre-rounded X)
constexpr int F_CVT_B   = 1;
constexpr int F_ROUND_C = 2;

__device__ __forceinline__ void cp_async16(uint32_t dst, const void* src) {
    asm volatile("cp.async.cg.shared.global [%0], [%1], 16;\n" :: "r"(dst), "l"(src));
}

__device__ __forceinline__ uint32_t f2tf32(float f) {
    uint32_t r;
    asm("cvt.rna.tf32.f32 %0, %1;" : "=r"(r) : "f"(f));
    return r;
}

__device__ __forceinline__ uint32_t cvt_bits(uint32_t raw) {
    return f2tf32(__uint_as_float(raw));
}

__device__ __forceinline__ void mbar_init(uint32_t addr, uint32_t cnt) {
    asm volatile("mbarrier.init.shared.b64 [%0], %1;" :: "r"(addr), "r"(cnt) : "memory");
}

__device__ __forceinline__ void mbar_arrive(uint32_t addr) {
    asm volatile("mbarrier.arrive.release.cta.shared::cta.b64 _, [%0];"
                 :: "r"(addr) : "memory");
}

__device__ __forceinline__ void mbar_wait(uint32_t mbar, uint32_t parity) {
    asm volatile(
        "{\n\t.reg .pred P1;\n\t"
        "LWAIT_%=:\n\t"
        "mbarrier.try_wait.parity.acquire.cta.shared::cta.b64 P1, [%0], %1, 0x989680;\n\t"
        "@P1 bra LDONE_%=;\n\t"
        "bra LWAIT_%=;\n\t"
        "LDONE_%=:\n\t}"
        :: "r"(mbar), "r"(parity) : "memory");
}

// ldmatrix x4 on f32 data: each m8n8.b16 tile == 8 rows x 4 f32 (16B rows);
// thread t gets element (t/4, t%4) of each tile.
__device__ __forceinline__ void ldsm_x4(uint32_t& r0, uint32_t& r1,
                                        uint32_t& r2, uint32_t& r3, uint32_t addr) {
    asm volatile("ldmatrix.sync.aligned.m8n8.x4.shared.b16 {%0,%1,%2,%3}, [%4];"
                 : "=r"(r0), "=r"(r1), "=r"(r2), "=r"(r3) : "r"(addr));
}

__device__ __forceinline__ void mma_tf32(float& c0, float& c1, float& c2, float& c3,
                                         uint32_t a0, uint32_t a1, uint32_t a2, uint32_t a3,
                                         uint32_t b0, uint32_t b1) {
    asm volatile(
        "mma.sync.aligned.m16n8k8.row.col.f32.tf32.tf32.f32 "
        "{%0,%1,%2,%3}, {%4,%5,%6,%7}, {%8,%9}, {%0,%1,%2,%3};"
        : "+f"(c0), "+f"(c1), "+f"(c2), "+f"(c3)
        : "r"(a0), "r"(a1), "r"(a2), "r"(a3), "r"(b0), "r"(b1));
}

} // namespace

// C[M,BN] = A[M,K] @ B[K,BN]; A row-major (lda), B row-major (BN). grid.x=M/BM.
__global__ __launch_bounds__(NTHREADS, 1)
void gemm_ws_tf32(float* __restrict__ C, const float* __restrict__ A,
                  const float* __restrict__ B, int K, size_t lda, int flags) {
    extern __shared__ __align__(1024) float smem[];
    const int tid = threadIdx.x, wid = tid >> 5, lane = tid & 31;
    const int m0 = blockIdx.x * BM;
    const uint32_t sbase = (uint32_t)__cvta_generic_to_shared(smem);
    const uint32_t dbase = sbase + CTRL_F * 4;
    const int KT = K / BK;

    // mbarriers: full[s] @ sbase+16s (async-group arrive, count=NPROD_THREADS),
    //            empty[s] @ +8 (count=NCONS)
    if (tid == 0) {
        #pragma unroll
        for (int s = 0; s < NSTAGE; ++s) {
            mbar_init(sbase + 16 * s,     NPROD_THREADS);
            mbar_init(sbase + 16 * s + 8, NCONS);
        }
    }
    __syncthreads();

    if (wid >= NCONS) {
        // ---------------- producers (4 warps, cp.async only) ----------------
        const int pt = tid - NCONS * 32;          // 0..127
        const float* Ab = A + (size_t)m0 * lda;

        for (int kt = 0; kt < KT; ++kt) {
            const int s = kt % NSTAGE;
            if (kt >= NSTAGE)
                mbar_wait(sbase + 16 * s + 8, (uint32_t)((kt / NSTAGE - 1) & 1));
            const float* Ak = Ab + (size_t)kt * BK;
            const float* Bk = B + (size_t)(kt * BK) * BN;
            const uint32_t dA = dbase + (uint32_t)(s * BUF) * 4u;
            const uint32_t dB = dA + (uint32_t)A_SZ * 4u;
            // A tile: 128 rows x 16 chunks; chunk c -> (row=c>>4, ch=c&15)
            #pragma unroll
            for (int i = 0; i < 16; ++i) {
                const int c = i * 128 + pt;
                const int row = c >> 4, ch = c & 15;
                cp_async16(dA + (uint32_t)(row * AS + ch * 4) * 4u,
                           Ak + (size_t)row * lda + ch * 4);
            }
            // B tile: 64 rows x 32 chunks; chunk c -> (row=c>>5, ch=c&31)
            #pragma unroll
            for (int i = 0; i < 16; ++i) {
                const int c = i * 128 + pt;
                const int row = c >> 5, ch = c & 31;
                cp_async16(dB + (uint32_t)(row * BS + ch * 4) * 4u,
                           Bk + (size_t)row * BN + ch * 4);
            }
            asm volatile("cp.async.mbarrier.arrive.noinc.shared::cta.b64 [%0];"
                         :: "r"(sbase + 16 * s) : "memory");
        }
    } else {
        // ------ consumers (8 warps): double-buffered frags; cvt A (B optional) ------
        const int wr = wid >> 2;              // 0..1 (64 rows each)
        const int wc = wid & 3;               // 0..3 (32 cols each)
        const int gid = lane >> 2, tig = lane & 3;
        const int lm_row = wr * 64 + (lane & 7) + ((lane >> 3) & 1) * 8;
        const int lm_k   = ((lane >> 3) >> 1) * 4;
        const bool cvtB = (flags & F_CVT_B) != 0;

        float acc[4][4][4];
        #pragma unroll
        for (int mi = 0; mi < 4; ++mi)
            #pragma unroll
            for (int ni = 0; ni < 4; ++ni)
                #pragma unroll
                for (int r = 0; r < 4; ++r) acc[mi][ni][r] = 0.0f;

        uint32_t a[2][4][4], b[2][4][2];

        for (int kt = 0; kt < KT; ++kt) {
            const int s = kt % NSTAGE;
            mbar_wait(sbase + 16 * s, (uint32_t)((kt / NSTAGE) & 1));

            const uint32_t aBase = dbase + (uint32_t)(s * BUF + lm_row * AS + lm_k) * 4u;
            const uint32_t* Bu = (const uint32_t*)(smem + CTRL_F + s * BUF + A_SZ);

            auto load_frag = [&](int kk, int d) {
                #pragma unroll
                for (int mi = 0; mi < 4; ++mi)
                    ldsm_x4(a[d][mi][0], a[d][mi][1], a[d][mi][2], a[d][mi][3],
                            aBase + (uint32_t)(mi * 16 * AS + kk) * 4u);
                #pragma unroll
                for (int ni = 0; ni < 4; ++ni) {
                    const int c = wc * 32 + ni * 8 + gid;
                    b[d][ni][0] = Bu[(kk + tig) * BS + c];
                    b[d][ni][1] = Bu[(kk + tig + 4) * BS + c];
                }
            };

            load_frag(0, 0);
            #pragma unroll
            for (int kq = 0; kq < BK / 8; ++kq) {
                const int d = kq & 1;
                if (kq < BK / 8 - 1) load_frag((kq + 1) * 8, d ^ 1);
                // A fragments: round-to-nearest tf32 (required for accuracy)
                #pragma unroll
                for (int mi = 0; mi < 4; ++mi)
                    #pragma unroll
                    for (int j = 0; j < 4; ++j)
                        a[d][mi][j] = cvt_bits(a[d][mi][j]);
                if (cvtB) {
                    #pragma unroll
                    for (int ni = 0; ni < 4; ++ni) {
                        b[d][ni][0] = cvt_bits(b[d][ni][0]);
                        b[d][ni][1] = cvt_bits(b[d][ni][1]);
                    }
                }
                #pragma unroll
                for (int mi = 0; mi < 4; ++mi)
                    #pragma unroll
                    for (int ni = 0; ni < 4; ++ni)
                        mma_tf32(acc[mi][ni][0], acc[mi][ni][1], acc[mi][ni][2], acc[mi][ni][3],
                                 a[d][mi][0], a[d][mi][1], a[d][mi][2], a[d][mi][3],
                                 b[d][ni][0], b[d][ni][1]);
            }
            __syncwarp();
            if (lane == 0) mbar_arrive(sbase + 16 * s + 8);
        }

        // epilogue (optionally round C to tf32 bits for the pre-rounded X path)
        const bool roundC = (flags & F_ROUND_C) != 0;
        #pragma unroll
        for (int mi = 0; mi < 4; ++mi) {
            #pragma unroll
            for (int ni = 0; ni < 4; ++ni) {
                float v0 = acc[mi][ni][0], v1 = acc[mi][ni][1];
                float v2 = acc[mi][ni][2], v3 = acc[mi][ni][3];
                if (roundC) {
                    v0 = __uint_as_float(f2tf32(v0));
                    v1 = __uint_as_float(f2tf32(v1));
                    v2 = __uint_as_float(f2tf32(v2));
                    v3 = __uint_as_float(f2tf32(v3));
                }
                const int row = m0 + wr * 64 + mi * 16 + gid;
                const int col = wc * 32 + ni * 8 + tig * 2;
                *(float2*)(C + (size_t)row * BN + col) = make_float2(v0, v1);
                *(float2*)(C + (size_t)(row + 8) * BN + col) = make_float2(v2, v3);
            }
        }
    }
}

extern "C" void kernel_launch(void* const* d_in, const int* in_sizes, int n_in,
                              void* d_out, int out_size) {
    const float* inputs  = (const float*)d_in[0];   // [16384, 512]
    const float* adj     = (const float*)d_in[1];   // [16384, 16384]
    const float* weights = (const float*)d_in[2];   // [512, 128]
    float* out = (float*)d_out;                     // [16384, 128]
    (void)in_sizes; (void)n_in; (void)out_size;

    cudaFuncSetAttribute(gemm_ws_tf32,
                         cudaFuncAttributeMaxDynamicSharedMemorySize, SMEM_BYTES);

    float* X = nullptr;
    cudaGetSymbolAddress((void**)&X, g_X);

    // G1: X = inputs @ W   (K=512): cvt B (raw weights), round X on output
    gemm_ws_tf32<<<N_ROWS / BM, NTHREADS, SMEM_BYTES>>>(
        X, inputs, weights, D_IN, D_IN, F_CVT_B | F_ROUND_C);
    // G2: out = adj @ X    (K=16384): B pre-rounded, plain f32 output
    gemm_ws_tf32<<<N_ROWS / BM, NTHREADS, SMEM_BYTES>>>(
        out, adj, X, N_ROWS, N_ROWS, 0);
}